// round 1
// baseline (speedup 1.0000x reference)
#include <cuda_runtime.h>
#include <math.h>

#define BB 2
#define NN 2048
#define DMODEL 512
#define HH 8
#define DK 64
#define MTOT (BB*NN)                 // 4096
#define HEADELEMS (BB*HH*NN*DK)      // 2097152
#define OUTHALF (MTOT*DMODEL)        // 2097152

// Scratch (allocation-free rule: __device__ globals)
__device__ float g_Qa[HEADELEMS];   // q + q2  (for att1)
__device__ float g_Qb[HEADELEMS];   // q + q1  (for att2)
__device__ float g_K1[HEADELEMS];
__device__ float g_K2[HEADELEMS];
__device__ float g_V1[HEADELEMS];
__device__ float g_V2[HEADELEMS];
__device__ float g_O1[OUTHALF];     // attn1 out, [B,N,H*64]
__device__ float g_O2[OUTHALF];

// ---------------------------------------------------------------------------
// Generic SGEMM: Y[m,o] = sum_k X[m,k] * W[o,k] + bias[o]
// M=4096, N=512, K=512. BM=BN=128, BK=16, 256 threads, 8x8 micro-tile.
// Epilogue modes control destination layout / accumulation.
// ---------------------------------------------------------------------------
#define GBM 128
#define GBN 128
#define GBK 16

#define MODE_QQ    0   // write v to D0 and D1 (heads layout)
#define MODE_ADD   1   // D0 += v (heads layout)
#define MODE_HEADS 2   // D0 = v (heads layout)
#define MODE_ROW   3   // D0[m*512+o] = v (row-major)

template<int MODE>
__global__ __launch_bounds__(256)
void gemm_k(const float* __restrict__ X, const float* __restrict__ W,
            const float* __restrict__ bias, float* __restrict__ D0,
            float* __restrict__ D1)
{
    __shared__ float As[GBK][GBM + 4];
    __shared__ float Bs[GBK][GBN + 4];

    const int tid  = threadIdx.x;
    const int m0   = blockIdx.y * GBM;
    const int n0   = blockIdx.x * GBN;
    const int tRow = tid >> 4;     // 0..15
    const int tCol = tid & 15;     // 0..15

    float acc[8][8];
#pragma unroll
    for (int i = 0; i < 8; i++)
#pragma unroll
        for (int j = 0; j < 8; j++) acc[i][j] = 0.f;

    const int lr = tid >> 2;          // 0..63
    const int lc = (tid & 3) << 2;    // 0,4,8,12
    const float* Xp = X + (size_t)(m0 + lr) * DMODEL + lc;
    const float* Wp = W + (size_t)(n0 + lr) * DMODEL + lc;

    for (int k0 = 0; k0 < DMODEL; k0 += GBK) {
#pragma unroll
        for (int p = 0; p < 2; p++) {
            const int row = lr + p * 64;
            float4 a = *(const float4*)(Xp + (size_t)p * 64 * DMODEL + k0);
            As[lc + 0][row] = a.x;
            As[lc + 1][row] = a.y;
            As[lc + 2][row] = a.z;
            As[lc + 3][row] = a.w;
            float4 b = *(const float4*)(Wp + (size_t)p * 64 * DMODEL + k0);
            Bs[lc + 0][row] = b.x;
            Bs[lc + 1][row] = b.y;
            Bs[lc + 2][row] = b.z;
            Bs[lc + 3][row] = b.w;
        }
        __syncthreads();

#pragma unroll
        for (int k = 0; k < GBK; k++) {
            float a[8], b[8];
            *(float4*)&a[0] = *(const float4*)&As[k][tRow * 8];
            *(float4*)&a[4] = *(const float4*)&As[k][tRow * 8 + 4];
            *(float4*)&b[0] = *(const float4*)&Bs[k][tCol * 8];
            *(float4*)&b[4] = *(const float4*)&Bs[k][tCol * 8 + 4];
#pragma unroll
            for (int i = 0; i < 8; i++)
#pragma unroll
                for (int j = 0; j < 8; j++)
                    acc[i][j] += a[i] * b[j];
        }
        __syncthreads();
    }

    // epilogue
#pragma unroll
    for (int i = 0; i < 8; i++) {
        const int m = m0 + tRow * 8 + i;
        const int bb = m >> 11;          // m / 2048
        const int n  = m & 2047;
#pragma unroll
        for (int j = 0; j < 8; j++) {
            const int o = n0 + tCol * 8 + j;
            const float v = acc[i][j] + bias[o];
            if (MODE == MODE_ROW) {
                D0[(size_t)m * DMODEL + o] = v;
            } else {
                const int h = o >> 6, d = o & 63;
                const size_t idx = (((size_t)(bb * HH + h)) * NN + n) * DK + d;
                if (MODE == MODE_QQ)      { D0[idx] = v; D1[idx] = v; }
                else if (MODE == MODE_ADD){ D0[idx] += v; }
                else                      { D0[idx] = v; }
            }
        }
    }
}

// ---------------------------------------------------------------------------
// Flash-style attention. One block = 64 Q rows of one (b,h,variant).
// grid = (N/64, B*H, 2). 256 threads, 16x16 layout, 4x4 micro-tiles.
// Online softmax with fused scale * attention_weights and -inf masking.
// Smem (dynamic, 66KB): Qt[d][r], Kt[d][c], Vs[c][d], Ps[r][c], cf[64], mk[64]
// ---------------------------------------------------------------------------
__global__ __launch_bounds__(256)
void attn_k(const float* __restrict__ Qa, const float* __restrict__ Qb,
            const float* __restrict__ K1, const float* __restrict__ K2,
            const float* __restrict__ V1, const float* __restrict__ V2,
            const int* __restrict__ mR, const int* __restrict__ mG,
            const float* __restrict__ wts,
            float* __restrict__ O1, float* __restrict__ O2)
{
    extern __shared__ float sm[];
    float* Qt = sm;              // [64][64] transposed: Qt[d*64 + r]
    float* Kt = sm + 4096;       // [64][64] transposed: Kt[d*64 + c]
    float* Vs = sm + 8192;       // [64][64] natural:    Vs[c*64 + d]
    float* Ps = sm + 12288;      // [64][64]:            Ps[r*64 + c]
    float* cf = sm + 16384;      // scale * weight per key
    float* mk = sm + 16448;      // mask flag per key

    const int var = blockIdx.z;
    const int bh  = blockIdx.y;
    const int bb  = bh >> 3;
    const int h   = bh & 7;
    const int qt  = blockIdx.x;

    const float* Q = (var ? Qb : Qa) + (size_t)bh * NN * DK + (size_t)qt * 64 * DK;
    const float* K = (var ? K2 : K1) + (size_t)bh * NN * DK;
    const float* V = (var ? V2 : V1) + (size_t)bh * NN * DK;
    const int*   msk = (var ? mG : mR) + bb * NN;
    const float* w   = wts + bb * NN;
    float* O = (var ? O2 : O1);

    const int tid  = threadIdx.x;
    const int tRow = tid >> 4;
    const int tCol = tid & 15;
    const int r0 = tRow * 4;
    const int c0 = tCol * 4;

    // load Q tile transposed
#pragma unroll
    for (int p = 0; p < 4; p++) {
        const int fi = tid + p * 256;
        const int r  = fi >> 4;
        const int c4 = (fi & 15) << 2;
        float4 v = *(const float4*)(Q + r * DK + c4);
        Qt[(c4 + 0) * 64 + r] = v.x;
        Qt[(c4 + 1) * 64 + r] = v.y;
        Qt[(c4 + 2) * 64 + r] = v.z;
        Qt[(c4 + 3) * 64 + r] = v.w;
    }

    float m_i[4], l_i[4], o[4][4];
#pragma unroll
    for (int i = 0; i < 4; i++) {
        m_i[i] = -INFINITY;
        l_i[i] = 0.f;
#pragma unroll
        for (int j = 0; j < 4; j++) o[i][j] = 0.f;
    }
    const float scale = 0.125f;   // 1/sqrt(64)

    for (int kt = 0; kt < NN / 64; kt++) {
        __syncthreads();   // previous PV done before overwriting tiles
#pragma unroll
        for (int p = 0; p < 4; p++) {
            const int fi = tid + p * 256;
            const int r  = fi >> 4;
            const int c4 = (fi & 15) << 2;
            float4 kv = *(const float4*)(K + (size_t)(kt * 64 + r) * DK + c4);
            Kt[(c4 + 0) * 64 + r] = kv.x;
            Kt[(c4 + 1) * 64 + r] = kv.y;
            Kt[(c4 + 2) * 64 + r] = kv.z;
            Kt[(c4 + 3) * 64 + r] = kv.w;
            float4 vv = *(const float4*)(V + (size_t)(kt * 64 + r) * DK + c4);
            *(float4*)(Vs + r * 64 + c4) = vv;
        }
        if (tid < 64) {
            cf[tid] = scale * w[kt * 64 + tid];
            mk[tid] = (float)msk[kt * 64 + tid];
        }
        __syncthreads();

        // S = Q K^T  (4x4 per thread)
        float s[4][4];
#pragma unroll
        for (int i = 0; i < 4; i++)
#pragma unroll
            for (int j = 0; j < 4; j++) s[i][j] = 0.f;

#pragma unroll 8
        for (int d = 0; d < 64; d++) {
            float4 q4 = *(const float4*)(Qt + d * 64 + r0);
            float4 k4 = *(const float4*)(Kt + d * 64 + c0);
            float aq[4] = {q4.x, q4.y, q4.z, q4.w};
            float ak[4] = {k4.x, k4.y, k4.z, k4.w};
#pragma unroll
            for (int i = 0; i < 4; i++)
#pragma unroll
                for (int j = 0; j < 4; j++)
                    s[i][j] += aq[i] * ak[j];
        }

        // apply scale*weight + mask
        float cfj[4], mkj[4];
#pragma unroll
        for (int j = 0; j < 4; j++) { cfj[j] = cf[c0 + j]; mkj[j] = mk[c0 + j]; }
#pragma unroll
        for (int i = 0; i < 4; i++)
#pragma unroll
            for (int j = 0; j < 4; j++)
                s[i][j] = (mkj[j] != 0.f) ? -INFINITY : s[i][j] * cfj[j];

        // online softmax update
        float f[4], mx[4];
#pragma unroll
        for (int i = 0; i < 4; i++) {
            float t = fmaxf(fmaxf(s[i][0], s[i][1]), fmaxf(s[i][2], s[i][3]));
            t = fmaxf(t, __shfl_xor_sync(0xffffffffu, t, 8));
            t = fmaxf(t, __shfl_xor_sync(0xffffffffu, t, 4));
            t = fmaxf(t, __shfl_xor_sync(0xffffffffu, t, 2));
            t = fmaxf(t, __shfl_xor_sync(0xffffffffu, t, 1));
            const float mn = fmaxf(m_i[i], t);
            mx[i] = fmaxf(mn, -1e30f);             // guard fully-masked rows
            f[i]  = __expf(m_i[i] - mx[i]);        // -inf -> 0, acc is 0 anyway
            m_i[i] = mn;
        }

        // p = exp(s - m), row-sums, stage P to smem
#pragma unroll
        for (int i = 0; i < 4; i++) {
            float p0 = __expf(s[i][0] - mx[i]);
            float p1 = __expf(s[i][1] - mx[i]);
            float p2 = __expf(s[i][2] - mx[i]);
            float p3 = __expf(s[i][3] - mx[i]);
            float rs = (p0 + p1) + (p2 + p3);
            rs += __shfl_xor_sync(0xffffffffu, rs, 8);
            rs += __shfl_xor_sync(0xffffffffu, rs, 4);
            rs += __shfl_xor_sync(0xffffffffu, rs, 2);
            rs += __shfl_xor_sync(0xffffffffu, rs, 1);
            l_i[i] = l_i[i] * f[i] + rs;
            float4 pr = make_float4(p0, p1, p2, p3);
            *(float4*)(Ps + (r0 + i) * 64 + c0) = pr;
        }
        __syncthreads();

        // O = O*f + P V
#pragma unroll
        for (int i = 0; i < 4; i++)
#pragma unroll
            for (int j = 0; j < 4; j++) o[i][j] *= f[i];

#pragma unroll 4
        for (int c = 0; c < 64; c++) {
            float4 v4 = *(const float4*)(Vs + c * 64 + c0);
            float av[4] = {v4.x, v4.y, v4.z, v4.w};
            float pv[4];
#pragma unroll
            for (int i = 0; i < 4; i++) pv[i] = Ps[(r0 + i) * 64 + c];
#pragma unroll
            for (int i = 0; i < 4; i++)
#pragma unroll
                for (int j = 0; j < 4; j++)
                    o[i][j] += pv[i] * av[j];
        }
    }

    // epilogue: normalize, write to [B, N, H*64]
#pragma unroll
    for (int i = 0; i < 4; i++) {
        const float inv = 1.f / l_i[i];
        const int n = qt * 64 + r0 + i;
        const size_t base = ((size_t)bb * NN + n) * DMODEL + h * DK + c0;
        float4 ov = make_float4(o[i][0] * inv, o[i][1] * inv,
                                o[i][2] * inv, o[i][3] * inv);
        *(float4*)(O + base) = ov;
    }
}

// ---------------------------------------------------------------------------
extern "C" void kernel_launch(void* const* d_in, const int* in_sizes, int n_in,
                              void* d_out, int out_size)
{
    const float* regions   = (const float*)d_in[0];
    const float* grids     = (const float*)d_in[1];
    const float* interests = (const float*)d_in[2];
    const int*   maskR     = (const int*)d_in[3];
    const int*   maskG     = (const int*)d_in[4];
    const float* wts       = (const float*)d_in[5];
    const float* Wq   = (const float*)d_in[6];
    const float* bq   = (const float*)d_in[7];
    const float* Wk   = (const float*)d_in[8];
    const float* bk   = (const float*)d_in[9];
    const float* Wv   = (const float*)d_in[10];
    const float* bv   = (const float*)d_in[11];
    const float* Wq12 = (const float*)d_in[12];
    const float* bq12 = (const float*)d_in[13];
    const float* Wo1  = (const float*)d_in[14];
    const float* bo1  = (const float*)d_in[15];
    const float* Wo2  = (const float*)d_in[16];
    const float* bo2  = (const float*)d_in[17];
    float* out = (float*)d_out;

    float *Qa, *Qb, *K1, *K2, *V1, *V2, *O1, *O2;
    cudaGetSymbolAddress((void**)&Qa, g_Qa);
    cudaGetSymbolAddress((void**)&Qb, g_Qb);
    cudaGetSymbolAddress((void**)&K1, g_K1);
    cudaGetSymbolAddress((void**)&K2, g_K2);
    cudaGetSymbolAddress((void**)&V1, g_V1);
    cudaGetSymbolAddress((void**)&V2, g_V2);
    cudaGetSymbolAddress((void**)&O1, g_O1);
    cudaGetSymbolAddress((void**)&O2, g_O2);

    const int ASMEM = (4 * 64 * 64 + 128) * (int)sizeof(float);  // 66048 B
    cudaFuncSetAttribute(attn_k, cudaFuncAttributeMaxDynamicSharedMemorySize, ASMEM);

    dim3 gg(DMODEL / GBN, MTOT / GBM);   // (4, 32)

    // Projections (epilogue fuses q+q2 / q+q1 and the heads-layout scatter)
    gemm_k<MODE_QQ>   <<<gg, 256>>>(interests, Wq,   bq,   Qa, Qb);
    gemm_k<MODE_ADD>  <<<gg, 256>>>(grids,     Wq12, bq12, Qa, nullptr); // Qa = q + q2
    gemm_k<MODE_ADD>  <<<gg, 256>>>(regions,   Wq12, bq12, Qb, nullptr); // Qb = q + q1
    gemm_k<MODE_HEADS><<<gg, 256>>>(regions,   Wk,   bk,   K1, nullptr);
    gemm_k<MODE_HEADS><<<gg, 256>>>(grids,     Wk,   bk,   K2, nullptr);
    gemm_k<MODE_HEADS><<<gg, 256>>>(regions,   Wv,   bv,   V1, nullptr);
    gemm_k<MODE_HEADS><<<gg, 256>>>(grids,     Wv,   bv,   V2, nullptr);

    // Both attentions in one launch (z selects variant)
    attn_k<<<dim3(NN / 64, BB * HH, 2), 256, ASMEM>>>(
        Qa, Qb, K1, K2, V1, V2, maskR, maskG, wts, O1, O2);

    // Output projections straight into d_out (out1 then out2)
    gemm_k<MODE_ROW><<<gg, 256>>>(O1, Wo1, bo1, out, nullptr);
    gemm_k<MODE_ROW><<<gg, 256>>>(O2, Wo2, bo2, out + OUTHALF, nullptr);
}